// round 4
// baseline (speedup 1.0000x reference)
#include <cuda_runtime.h>
#include <cstddef>

#define QL 1024
#define BATCH 2
#define DM 1024
#define NH 16
#define DH 64
#define QB 2048            // Q*B rows
#define H3 3072            // 3*NH*DH
#define JR 2047            // 2*Q-1
#define SCALEF 0.125f      // 1/sqrt(64)
#define EPSF 1e-5f

// -------- scratch (device globals; no allocations allowed) --------
__device__ float g_H[(size_t)QB * H3];          // qkv heads     25 MB
__device__ float g_RF[(size_t)QL * DM];         // r @ W_r_fw     4 MB
__device__ float g_RB[(size_t)QL * DM];         // r @ W_r_bw     4 MB
__device__ float g_AC[(size_t)32 * QL * QL];    // AC scores    134 MB
__device__ float g_BD[(size_t)32 * QL * JR];    // BD raw       268 MB
__device__ float g_P[(size_t)32 * QL * QL];     // softmax      134 MB
__device__ float g_V[(size_t)QB * DM];          // attention vec  8 MB
__device__ float g_AO[(size_t)QB * DM];         // attn_out       8 MB

// ================= generic NN SGEMM: C[M,N] = A[M,K] @ B[K,N] ==============
// 128x128 tile, bk=8, 256 threads, 8x8 per-thread micro-tile.
// Requires M%128==0, N%128==0, K%8==0 (true for all call sites).
__global__ void __launch_bounds__(256) gemm_nn_kernel(
    const float* __restrict__ A, const float* __restrict__ B,
    float* __restrict__ C, int M, int N, int K) {
  __shared__ float As[8][128];
  __shared__ float Bs[8][128];
  const int tid = threadIdx.x;
  const int bx = blockIdx.x, by = blockIdx.y;
  const int tx = tid & 15, ty = tid >> 4;
  const int arow = tid >> 1, acol = (tid & 1) * 4;
  const int brow = tid >> 5, bcol = (tid & 31) * 4;
  const float* Ag = A + (size_t)(by * 128 + arow) * K + acol;
  const float* Bg = B + (size_t)brow * N + bx * 128 + bcol;
  float acc[8][8] = {};
  for (int k0 = 0; k0 < K; k0 += 8) {
    float4 av = *(const float4*)(Ag + k0);
    As[acol + 0][arow] = av.x;
    As[acol + 1][arow] = av.y;
    As[acol + 2][arow] = av.z;
    As[acol + 3][arow] = av.w;
    float4 bv = *(const float4*)(Bg + (size_t)k0 * N);
    *(float4*)&Bs[brow][bcol] = bv;
    __syncthreads();
#pragma unroll
    for (int k = 0; k < 8; ++k) {
      float a[8], b[8];
#pragma unroll
      for (int u = 0; u < 8; ++u) a[u] = As[k][ty * 8 + u];
#pragma unroll
      for (int v = 0; v < 8; ++v) b[v] = Bs[k][tx * 8 + v];
#pragma unroll
      for (int u = 0; u < 8; ++u)
#pragma unroll
        for (int v = 0; v < 8; ++v) acc[u][v] += a[u] * b[v];
    }
    __syncthreads();
  }
  float* Cg = C + (size_t)(by * 128 + ty * 8) * N + bx * 128 + tx * 8;
#pragma unroll
  for (int u = 0; u < 8; ++u)
#pragma unroll
    for (int v = 0; v < 8; ++v)
      Cg[(size_t)u * N + v] = acc[u][v];
}

// ================= AC: AC[bn][i][j] = (q_i + rwb_n) . k_j  (K=64, NT) ======
__global__ void __launch_bounds__(256) ac_kernel(
    const float* __restrict__ H, const float* __restrict__ r_w_bias,
    float* __restrict__ AC) {
  const int bn = blockIdx.z, b = bn >> 4, n = bn & 15;
  const int i0 = blockIdx.y * 128, j0 = blockIdx.x * 128;
  const int tid = threadIdx.x;
  __shared__ float As[32][128];
  __shared__ float Bs[32][128];
  const int row = tid >> 1;
  const int c4 = (tid & 1) * 4;
  const float* qg = H + (size_t)((i0 + row) * 2 + b) * H3 + n * DH;
  const float* kg = H + (size_t)((j0 + row) * 2 + b) * H3 + DM + n * DH;
  const float* bias = r_w_bias + n * DH;
  const int tx = tid & 15, ty = tid >> 4;
  float acc[8][8] = {};
  for (int kc = 0; kc < DH; kc += 32) {
#pragma unroll
    for (int kk = 0; kk < 32; kk += 8) {
      int col = kk + c4;
      float4 av = *(const float4*)(qg + kc + col);
      As[col + 0][row] = av.x + bias[kc + col + 0];
      As[col + 1][row] = av.y + bias[kc + col + 1];
      As[col + 2][row] = av.z + bias[kc + col + 2];
      As[col + 3][row] = av.w + bias[kc + col + 3];
      float4 bv = *(const float4*)(kg + kc + col);
      Bs[col + 0][row] = bv.x;
      Bs[col + 1][row] = bv.y;
      Bs[col + 2][row] = bv.z;
      Bs[col + 3][row] = bv.w;
    }
    __syncthreads();
#pragma unroll
    for (int k = 0; k < 32; ++k) {
      float a[8], bb[8];
#pragma unroll
      for (int u = 0; u < 8; ++u) a[u] = As[k][ty * 8 + u];
#pragma unroll
      for (int v = 0; v < 8; ++v) bb[v] = Bs[k][tx * 8 + v];
#pragma unroll
      for (int u = 0; u < 8; ++u)
#pragma unroll
        for (int v = 0; v < 8; ++v) acc[u][v] += a[u] * bb[v];
    }
    __syncthreads();
  }
  float* out = AC + ((size_t)bn * QL + i0 + ty * 8) * QL + j0 + tx * 8;
#pragma unroll
  for (int u = 0; u < 8; ++u)
#pragma unroll
    for (int v = 0; v < 8; ++v)
      out[(size_t)u * QL + v] = acc[u][v];
}

// ========== BD: BD[bn][i][jr] = (q_i + rrb_n) . r_k[jr]  (K=64, NT) ========
// r_k[jr] = RF[jr] if jr<1024 else RB[2046-jr]
__global__ void __launch_bounds__(256) bd_kernel(
    const float* __restrict__ H, const float* __restrict__ RF,
    const float* __restrict__ RB, const float* __restrict__ r_r_bias,
    float* __restrict__ BD) {
  const int bn = blockIdx.z, b = bn >> 4, n = bn & 15;
  const int i0 = blockIdx.y * 128, j0 = blockIdx.x * 128;
  const int tid = threadIdx.x;
  __shared__ float As[32][128];
  __shared__ float Bs[32][128];
  const int row = tid >> 1;
  const int c4 = (tid & 1) * 4;
  const float* qg = H + (size_t)((i0 + row) * 2 + b) * H3 + n * DH;
  const int jr = j0 + row;
  const float* rg = nullptr;
  if (jr < QL)
    rg = RF + (size_t)jr * DM + n * DH;
  else if (jr < JR)
    rg = RB + (size_t)(2046 - jr) * DM + n * DH;
  const float* bias = r_r_bias + n * DH;
  const int tx = tid & 15, ty = tid >> 4;
  float acc[8][8] = {};
  for (int kc = 0; kc < DH; kc += 32) {
#pragma unroll
    for (int kk = 0; kk < 32; kk += 8) {
      int col = kk + c4;
      float4 av = *(const float4*)(qg + kc + col);
      As[col + 0][row] = av.x + bias[kc + col + 0];
      As[col + 1][row] = av.y + bias[kc + col + 1];
      As[col + 2][row] = av.z + bias[kc + col + 2];
      As[col + 3][row] = av.w + bias[kc + col + 3];
      float4 bv = rg ? *(const float4*)(rg + kc + col) : make_float4(0.f, 0.f, 0.f, 0.f);
      Bs[col + 0][row] = bv.x;
      Bs[col + 1][row] = bv.y;
      Bs[col + 2][row] = bv.z;
      Bs[col + 3][row] = bv.w;
    }
    __syncthreads();
#pragma unroll
    for (int k = 0; k < 32; ++k) {
      float a[8], bb[8];
#pragma unroll
      for (int u = 0; u < 8; ++u) a[u] = As[k][ty * 8 + u];
#pragma unroll
      for (int v = 0; v < 8; ++v) bb[v] = Bs[k][tx * 8 + v];
#pragma unroll
      for (int u = 0; u < 8; ++u)
#pragma unroll
        for (int v = 0; v < 8; ++v) acc[u][v] += a[u] * bb[v];
    }
    __syncthreads();
  }
  float* out = BD + (size_t)bn * QL * JR + (size_t)(i0 + ty * 8) * JR + j0 + tx * 8;
#pragma unroll
  for (int u = 0; u < 8; ++u)
#pragma unroll
    for (int v = 0; v < 8; ++v) {
      int j = j0 + tx * 8 + v;
      if (j < JR) out[(size_t)u * JR + v] = acc[u][v];
    }
}

// ========== softmax: P[bn][i][j] = softmax_j((AC + BD_shifted)*SCALE) ======
__global__ void __launch_bounds__(256) softmax_kernel(
    const float* __restrict__ AC, const float* __restrict__ BD,
    const unsigned char* __restrict__ mask, float* __restrict__ P) {
  const int i = blockIdx.x, bn = blockIdx.y, b = bn >> 4;
  const float* ac = AC + ((size_t)bn * QL + i) * QL;
  const float* bd = BD + (size_t)bn * QL * JR + (size_t)i * JR + (QL - 1 - i);
  float* p = P + ((size_t)bn * QL + i) * QL;
  const int tid = threadIdx.x;
  float s[4];
  float mx = -3.4e38f;
#pragma unroll
  for (int t = 0; t < 4; ++t) {
    int j = tid + t * 256;
    float v = (ac[j] + bd[j]) * SCALEF;
    if (mask[j * BATCH + b]) v = -1e30f;
    s[t] = v;
    mx = fmaxf(mx, v);
  }
  __shared__ float red[8];
  __shared__ float red2[8];
#pragma unroll
  for (int o = 16; o; o >>= 1) mx = fmaxf(mx, __shfl_xor_sync(0xffffffffu, mx, o));
  if ((tid & 31) == 0) red[tid >> 5] = mx;
  __syncthreads();
  float bm = red[0];
#pragma unroll
  for (int k = 1; k < 8; ++k) bm = fmaxf(bm, red[k]);
  float sum = 0.f;
#pragma unroll
  for (int t = 0; t < 4; ++t) {
    s[t] = __expf(s[t] - bm);
    sum += s[t];
  }
#pragma unroll
  for (int o = 16; o; o >>= 1) sum += __shfl_xor_sync(0xffffffffu, sum, o);
  if ((tid & 31) == 0) red2[tid >> 5] = sum;
  __syncthreads();
  float tot = 0.f;
#pragma unroll
  for (int k = 0; k < 8; ++k) tot += red2[k];
  float inv = 1.f / tot;
#pragma unroll
  for (int t = 0; t < 4; ++t) p[tid + t * 256] = s[t] * inv;
}

// ========== PV: vec[i,b,n,:] = sum_j P[bn][i][j] * v[j,b,n,:]  =============
// M=1024(i), N=64(d), K=1024(j). 128x64 tile, 256 threads, 8x4 micro.
__global__ void __launch_bounds__(256) pv_kernel(
    const float* __restrict__ P, const float* __restrict__ H,
    float* __restrict__ V) {
  const int bn = blockIdx.y, b = bn >> 4, n = bn & 15;
  const int i0 = blockIdx.x * 128;
  const int tid = threadIdx.x;
  __shared__ float As[8][128];
  __shared__ float Bs[8][64];
  const int arow = tid >> 1, ac4 = (tid & 1) * 4;
  const int bkk = tid >> 5, bd2 = (tid & 31) * 2;
  const float* Ag = P + ((size_t)bn * QL + i0 + arow) * QL + ac4;
  const int tx = tid & 15, ty = tid >> 4;
  float acc[8][4] = {};
  for (int k0 = 0; k0 < QL; k0 += 8) {
    float4 av = *(const float4*)(Ag + k0);
    As[ac4 + 0][arow] = av.x;
    As[ac4 + 1][arow] = av.y;
    As[ac4 + 2][arow] = av.z;
    As[ac4 + 3][arow] = av.w;
    const float* vg = H + (size_t)((k0 + bkk) * 2 + b) * H3 + 2 * DM + n * DH + bd2;
    float2 bv = *(const float2*)vg;
    Bs[bkk][bd2] = bv.x;
    Bs[bkk][bd2 + 1] = bv.y;
    __syncthreads();
#pragma unroll
    for (int k = 0; k < 8; ++k) {
      float a[8], bb[4];
#pragma unroll
      for (int u = 0; u < 8; ++u) a[u] = As[k][ty * 8 + u];
#pragma unroll
      for (int v = 0; v < 4; ++v) bb[v] = Bs[k][tx * 4 + v];
#pragma unroll
      for (int u = 0; u < 8; ++u)
#pragma unroll
        for (int v = 0; v < 4; ++v) acc[u][v] += a[u] * bb[v];
    }
    __syncthreads();
  }
#pragma unroll
  for (int u = 0; u < 8; ++u) {
    float* out = V + (size_t)((i0 + ty * 8 + u) * 2 + b) * DM + n * DH + tx * 4;
#pragma unroll
    for (int v = 0; v < 4; ++v) out[v] = acc[u][v];
  }
}

// ========== residual + LayerNorm ==========================================
__global__ void __launch_bounds__(256) ln_kernel(
    const float* __restrict__ w, const float* __restrict__ AO,
    const float* __restrict__ gamma, const float* __restrict__ beta,
    float* __restrict__ out) {
  const int row = blockIdx.x;
  const int tid = threadIdx.x;
  const float* x1 = w + (size_t)row * DM;
  const float* x2 = AO + (size_t)row * DM;
  float x[4];
  float s = 0.f, s2 = 0.f;
#pragma unroll
  for (int t = 0; t < 4; ++t) {
    int d = tid + t * 256;
    x[t] = x1[d] + x2[d];
    s += x[t];
    s2 += x[t] * x[t];
  }
  __shared__ float r1[8], r2[8];
#pragma unroll
  for (int o = 16; o; o >>= 1) {
    s += __shfl_xor_sync(0xffffffffu, s, o);
    s2 += __shfl_xor_sync(0xffffffffu, s2, o);
  }
  if ((tid & 31) == 0) { r1[tid >> 5] = s; r2[tid >> 5] = s2; }
  __syncthreads();
  s = 0.f; s2 = 0.f;
#pragma unroll
  for (int k = 0; k < 8; ++k) { s += r1[k]; s2 += r2[k]; }
  const float mu = s * (1.f / DM);
  const float var = s2 * (1.f / DM) - mu * mu;
  const float inv = rsqrtf(var + EPSF);
  float* o = out + (size_t)row * DM;
#pragma unroll
  for (int t = 0; t < 4; ++t) {
    int d = tid + t * 256;
    o[d] = (x[t] - mu) * inv * gamma[d] + beta[d];
  }
}

// ===========================================================================
extern "C" void kernel_launch(void* const* d_in, const int* in_sizes, int n_in,
                              void* d_out, int out_size) {
  const float* w    = (const float*)d_in[0];   // [1024,2,1024]
  const float* r    = (const float*)d_in[1];   // [1024,1024]
  const float* rwb  = (const float*)d_in[2];   // [16,64]
  const float* rrb  = (const float*)d_in[3];   // [16,64]
  const unsigned char* mask = (const unsigned char*)d_in[4];  // [1024,2] bool
  const float* Wqkv = (const float*)d_in[5];   // [1024,3072]
  const float* Wrf  = (const float*)d_in[6];   // [1024,1024]
  const float* Wrb  = (const float*)d_in[7];   // [1024,1024]
  const float* Wo   = (const float*)d_in[8];   // [1024,1024]
  const float* lng  = (const float*)d_in[9];   // [1024]
  const float* lnb  = (const float*)d_in[10];  // [1024]
  float* out = (float*)d_out;                  // [1024,2,1024]

  void *pH, *pRF, *pRB, *pAC, *pBD, *pP, *pV, *pAO;
  cudaGetSymbolAddress(&pH, g_H);
  cudaGetSymbolAddress(&pRF, g_RF);
  cudaGetSymbolAddress(&pRB, g_RB);
  cudaGetSymbolAddress(&pAC, g_AC);
  cudaGetSymbolAddress(&pBD, g_BD);
  cudaGetSymbolAddress(&pP, g_P);
  cudaGetSymbolAddress(&pV, g_V);
  cudaGetSymbolAddress(&pAO, g_AO);
  float* H  = (float*)pH;
  float* RF = (float*)pRF;
  float* RB = (float*)pRB;
  float* AC = (float*)pAC;
  float* BD = (float*)pBD;
  float* P  = (float*)pP;
  float* V  = (float*)pV;
  float* AO = (float*)pAO;

  // 1) qkv projection: H[2048,3072] = w2d @ W_qkv
  gemm_nn_kernel<<<dim3(H3 / 128, QB / 128), 256>>>(w, Wqkv, H, QB, H3, DM);
  // 2) r projections
  gemm_nn_kernel<<<dim3(DM / 128, QL / 128), 256>>>(r, Wrf, RF, QL, DM, DM);
  gemm_nn_kernel<<<dim3(DM / 128, QL / 128), 256>>>(r, Wrb, RB, QL, DM, DM);
  // 3) AC scores
  ac_kernel<<<dim3(QL / 128, QL / 128, 32), 256>>>(H, rwb, AC);
  // 4) BD raw scores (jr = 0..2046)
  bd_kernel<<<dim3((JR + 127) / 128, QL / 128, 32), 256>>>(H, RF, RB, rrb, BD);
  // 5) shift + mask + softmax
  softmax_kernel<<<dim3(QL, 32), 256>>>(AC, BD, mask, P);
  // 6) P @ V
  pv_kernel<<<dim3(QL / 128, 32), 256>>>(P, H, V);
  // 7) output projection
  gemm_nn_kernel<<<dim3(DM / 128, QB / 128), 256>>>(V, Wo, AO, QB, DM, DM);
  // 8) residual + layernorm
  ln_kernel<<<QB, 256>>>(w, AO, lng, lnb, out);
}

// round 9
// speedup vs baseline: 2.5982x; 2.5982x over previous
#include <cuda_runtime.h>
#include <cuda_bf16.h>
#include <cstdint>
#include <cstddef>

#define QL 1024
#define BATCH 2
#define DM 1024
#define NH 16
#define DH 64
#define QB 2048            // Q*B rows
#define H3 3072            // 3*NH*DH
#define JR 2047            // 2*Q-1
#define SCALEF 0.125f      // 1/sqrt(64)
#define EPSF 1e-5f

// -------- scratch (device globals; no allocations allowed) --------
__device__ float g_H[(size_t)QB * H3];          // qkv heads     25 MB
__device__ float g_RF[(size_t)QL * DM];         // r @ W_r_fw     4 MB
__device__ float g_RB[(size_t)QL * DM];         // r @ W_r_bw     4 MB
__device__ float g_AC[(size_t)32 * QL * QL];    // AC scores    134 MB
__device__ float g_BD[(size_t)32 * QL * JR];    // BD raw       268 MB
__device__ float g_P[(size_t)32 * QL * QL];     // softmax      134 MB
__device__ float g_V[(size_t)QB * DM];          // attention vec  8 MB
__device__ float g_AO[(size_t)QB * DM];         // attn_out       8 MB

// split bf16 operands
__device__ __nv_bfloat16 g_Awh[(size_t)QB * DM], g_Awl[(size_t)QB * DM];
__device__ __nv_bfloat16 g_rh[(size_t)QL * DM], g_rl[(size_t)QL * DM];
__device__ __nv_bfloat16 g_Vh[(size_t)QB * DM], g_Vl[(size_t)QB * DM];
__device__ __nv_bfloat16 g_Wqt_h[(size_t)H3 * DM], g_Wqt_l[(size_t)H3 * DM];
__device__ __nv_bfloat16 g_Wft_h[(size_t)DM * DM], g_Wft_l[(size_t)DM * DM];
__device__ __nv_bfloat16 g_Wbt_h[(size_t)DM * DM], g_Wbt_l[(size_t)DM * DM];
__device__ __nv_bfloat16 g_Wot_h[(size_t)DM * DM], g_Wot_l[(size_t)DM * DM];

// ======================= small PTX helpers (portable) ======================
__device__ __forceinline__ uint32_t smem_to_u32(const void* p) {
  uint32_t a;
  asm("{ .reg .u64 t; cvta.to.shared.u64 t, %1; cvt.u32.u64 %0, t; }"
      : "=r"(a) : "l"(p));
  return a;
}
__device__ __forceinline__ void ldsm4(uint32_t* r, uint32_t a) {
  asm volatile("ldmatrix.sync.aligned.m8n8.x4.shared.b16 {%0,%1,%2,%3}, [%4];"
               : "=r"(r[0]), "=r"(r[1]), "=r"(r[2]), "=r"(r[3]) : "r"(a));
}
__device__ __forceinline__ void mma_bf16(float* c, const uint32_t* a,
                                         const uint32_t* b) {
  asm volatile(
      "mma.sync.aligned.m16n8k16.row.col.f32.bf16.bf16.f32 "
      "{%0,%1,%2,%3},{%4,%5,%6,%7},{%8,%9},{%0,%1,%2,%3};"
      : "+f"(c[0]), "+f"(c[1]), "+f"(c[2]), "+f"(c[3])
      : "r"(a[0]), "r"(a[1]), "r"(a[2]), "r"(a[3]), "r"(b[0]), "r"(b[1]));
}

// ================= elementwise fp32 -> bf16 hi/lo split ====================
__global__ void __launch_bounds__(256) split_kernel(
    const float* __restrict__ X, __nv_bfloat16* __restrict__ Xh,
    __nv_bfloat16* __restrict__ Xl, int n4) {
  int i = blockIdx.x * 256 + threadIdx.x;
  if (i >= n4) return;
  float4 v = ((const float4*)X)[i];
  __nv_bfloat16 h0 = __float2bfloat16(v.x);
  __nv_bfloat16 h1 = __float2bfloat16(v.y);
  __nv_bfloat16 h2 = __float2bfloat16(v.z);
  __nv_bfloat16 h3 = __float2bfloat16(v.w);
  __nv_bfloat16 l0 = __float2bfloat16(v.x - __bfloat162float(h0));
  __nv_bfloat16 l1 = __float2bfloat16(v.y - __bfloat162float(h1));
  __nv_bfloat16 l2 = __float2bfloat16(v.z - __bfloat162float(h2));
  __nv_bfloat16 l3 = __float2bfloat16(v.w - __bfloat162float(h3));
  ((__nv_bfloat162*)Xh)[2 * i]     = __halves2bfloat162(h0, h1);
  ((__nv_bfloat162*)Xh)[2 * i + 1] = __halves2bfloat162(h2, h3);
  ((__nv_bfloat162*)Xl)[2 * i]     = __halves2bfloat162(l0, l1);
  ((__nv_bfloat162*)Xl)[2 * i + 1] = __halves2bfloat162(l2, l3);
}

// ============== transpose + split: W[K,N] fp32 -> Wt[N,K] bf16 hi/lo =======
__global__ void __launch_bounds__(256) tsplit_kernel(
    const float* __restrict__ W, __nv_bfloat16* __restrict__ Oht,
    __nv_bfloat16* __restrict__ Olt, int K, int N) {
  __shared__ float t[32][33];
  const int n0 = blockIdx.x * 32, k0 = blockIdx.y * 32;
  const int tx = threadIdx.x, ty = threadIdx.y;
  for (int r = ty; r < 32; r += 8)
    t[r][tx] = W[(size_t)(k0 + r) * N + n0 + tx];
  __syncthreads();
  for (int r = ty; r < 32; r += 8) {
    float v = t[tx][r];  // = W[k0+tx][n0+r]
    __nv_bfloat16 h = __float2bfloat16(v);
    __nv_bfloat16 l = __float2bfloat16(v - __bfloat162float(h));
    size_t o = (size_t)(n0 + r) * K + k0 + tx;
    Oht[o] = h;
    Olt[o] = l;
  }
}

// ============ mma.sync bf16 NT GEMM with hi/lo split (3 terms) =============
// C[M,N] fp32 = Ah·Bh^T + Ah·Bl^T + Al·Bh^T
// A* [M,K] bf16 row-major, B* [N,K] bf16 row-major (both K-major).
// Block tile 128x128, 8 warps (4x2), warp tile 32x64, K-chunk 32.
#define STR 40  // smem row stride in bf16 (80B): conflict-free ldmatrix
__global__ void __launch_bounds__(256) mma_gemm_nt(
    const __nv_bfloat16* __restrict__ Ah, const __nv_bfloat16* __restrict__ Al,
    const __nv_bfloat16* __restrict__ Bh, const __nv_bfloat16* __restrict__ Bl,
    float* __restrict__ C, int M, int N, int K) {
  __shared__ __nv_bfloat16 sAh[128 * STR], sAl[128 * STR];
  __shared__ __nv_bfloat16 sBh[128 * STR], sBl[128 * STR];
  const int tid = threadIdx.x, wid = tid >> 5, lane = tid & 31;
  const int m0 = blockIdx.y * 128, n0 = blockIdx.x * 128;
  const int wm = (wid & 3) * 32;   // warp m offset in tile
  const int wn = (wid >> 2) * 64;  // warp n offset in tile

  // ldmatrix source offsets (per-warp, constant part)
  const int aRow = wm + (lane & 15);
  const int aCol = (lane >> 4) * 8;
  const int bRow = wn + (lane & 7) + ((lane >> 4) & 1) * 8;
  const int bCol = ((lane >> 3) & 1) * 8;
  const uint32_t aOffH = smem_to_u32(sAh) + (uint32_t)(aRow * STR + aCol) * 2;
  const uint32_t aOffL = smem_to_u32(sAl) + (uint32_t)(aRow * STR + aCol) * 2;
  const uint32_t bOffH = smem_to_u32(sBh) + (uint32_t)(bRow * STR + bCol) * 2;
  const uint32_t bOffL = smem_to_u32(sBl) + (uint32_t)(bRow * STR + bCol) * 2;

  float acc[2][8][4] = {};

  const int row2 = tid >> 2, q2 = (tid & 3) * 8;  // tile-load mapping (a)
  for (int c = 0; c < K; c += 32) {
    __syncthreads();
#pragma unroll
    for (int t = 0; t < 2; ++t) {
      int row = row2 + t * 64;
      size_t ga = (size_t)(m0 + row) * K + c + q2;
      size_t gb = (size_t)(n0 + row) * K + c + q2;
      *(uint4*)&sAh[row * STR + q2] = *(const uint4*)(Ah + ga);
      *(uint4*)&sAl[row * STR + q2] = *(const uint4*)(Al + ga);
      *(uint4*)&sBh[row * STR + q2] = *(const uint4*)(Bh + gb);
      *(uint4*)&sBl[row * STR + q2] = *(const uint4*)(Bl + gb);
    }
    __syncthreads();
#pragma unroll
    for (int ks = 0; ks < 2; ++ks) {
      const uint32_t kso = (uint32_t)(ks * 16) * 2;
      uint32_t ah[2][4], al[2][4], bh[8][2], bl[8][2];
#pragma unroll
      for (int mt = 0; mt < 2; ++mt) {
        const uint32_t mo = (uint32_t)(mt * 16 * STR) * 2;
        ldsm4(ah[mt], aOffH + mo + kso);
        ldsm4(al[mt], aOffL + mo + kso);
      }
#pragma unroll
      for (int np = 0; np < 4; ++np) {  // each x4 covers two n-tiles
        const uint32_t no = (uint32_t)(np * 16 * STR) * 2;
        uint32_t r[4];
        ldsm4(r, bOffH + no + kso);
        bh[2 * np][0] = r[0]; bh[2 * np][1] = r[1];
        bh[2 * np + 1][0] = r[2]; bh[2 * np + 1][1] = r[3];
        ldsm4(r, bOffL + no + kso);
        bl[2 * np][0] = r[0]; bl[2 * np][1] = r[1];
        bl[2 * np + 1][0] = r[2]; bl[2 * np + 1][1] = r[3];
      }
#pragma unroll
      for (int mt = 0; mt < 2; ++mt)
#pragma unroll
        for (int nt = 0; nt < 8; ++nt) {
          mma_bf16(acc[mt][nt], ah[mt], bh[nt]);
          mma_bf16(acc[mt][nt], ah[mt], bl[nt]);
          mma_bf16(acc[mt][nt], al[mt], bh[nt]);
        }
    }
  }

  // epilogue: C frag m16n8 layout
  const int cr = lane >> 2, cc = (lane & 3) * 2;
#pragma unroll
  for (int mt = 0; mt < 2; ++mt) {
    const int r = m0 + wm + mt * 16 + cr;
#pragma unroll
    for (int nt = 0; nt < 8; ++nt) {
      const int col = n0 + wn + nt * 8 + cc;
      float2 v0 = make_float2(acc[mt][nt][0], acc[mt][nt][1]);
      float2 v1 = make_float2(acc[mt][nt][2], acc[mt][nt][3]);
      *(float2*)&C[(size_t)r * N + col] = v0;
      *(float2*)&C[(size_t)(r + 8) * N + col] = v1;
    }
  }
}

// ================= AC: AC[bn][i][j] = (q_i + rwb_n) . k_j  (K=64, NT) ======
__global__ void __launch_bounds__(256) ac_kernel(
    const float* __restrict__ H, const float* __restrict__ r_w_bias,
    float* __restrict__ AC) {
  const int bn = blockIdx.z, b = bn >> 4, n = bn & 15;
  const int i0 = blockIdx.y * 128, j0 = blockIdx.x * 128;
  const int tid = threadIdx.x;
  __shared__ float As[32][128];
  __shared__ float Bs[32][128];
  const int row = tid >> 1;
  const int c4 = (tid & 1) * 4;
  const float* qg = H + (size_t)((i0 + row) * 2 + b) * H3 + n * DH;
  const float* kg = H + (size_t)((j0 + row) * 2 + b) * H3 + DM + n * DH;
  const float* bias = r_w_bias + n * DH;
  const int tx = tid & 15, ty = tid >> 4;
  float acc[8][8] = {};
  for (int kc = 0; kc < DH; kc += 32) {
#pragma unroll
    for (int kk = 0; kk < 32; kk += 8) {
      int col = kk + c4;
      float4 av = *(const float4*)(qg + kc + col);
      As[col + 0][row] = av.x + bias[kc + col + 0];
      As[col + 1][row] = av.y + bias[kc + col + 1];
      As[col + 2][row] = av.z + bias[kc + col + 2];
      As[col + 3][row] = av.w + bias[kc + col + 3];
      float4 bv = *(const float4*)(kg + kc + col);
      Bs[col + 0][row] = bv.x;
      Bs[col + 1][row] = bv.y;
      Bs[col + 2][row] = bv.z;
      Bs[col + 3][row] = bv.w;
    }
    __syncthreads();
#pragma unroll
    for (int k = 0; k < 32; ++k) {
      float a[8], bb[8];
#pragma unroll
      for (int u = 0; u < 8; ++u) a[u] = As[k][ty * 8 + u];
#pragma unroll
      for (int v = 0; v < 8; ++v) bb[v] = Bs[k][tx * 8 + v];
#pragma unroll
      for (int u = 0; u < 8; ++u)
#pragma unroll
        for (int v = 0; v < 8; ++v) acc[u][v] += a[u] * bb[v];
    }
    __syncthreads();
  }
  float* out = AC + ((size_t)bn * QL + i0 + ty * 8) * QL + j0 + tx * 8;
#pragma unroll
  for (int u = 0; u < 8; ++u)
#pragma unroll
    for (int v = 0; v < 8; ++v)
      out[(size_t)u * QL + v] = acc[u][v];
}

// ========== BD: BD[bn][i][jr] = (q_i + rrb_n) . r_k[jr]  (K=64, NT) ========
// r_k[jr] = RF[jr] if jr<1024 else RB[2046-jr]
// band skip: only tiles with i0+j0 in [769, 2046] are ever read by softmax.
__global__ void __launch_bounds__(256) bd_kernel(
    const float* __restrict__ H, const float* __restrict__ RF,
    const float* __restrict__ RB, const float* __restrict__ r_r_bias,
    float* __restrict__ BD) {
  const int bn = blockIdx.z, b = bn >> 4, n = bn & 15;
  const int i0 = blockIdx.y * 128, j0 = blockIdx.x * 128;
  if (i0 + j0 < 769 || i0 + j0 > 2046) return;  // outside rel-shift band
  const int tid = threadIdx.x;
  __shared__ float As[32][128];
  __shared__ float Bs[32][128];
  const int row = tid >> 1;
  const int c4 = (tid & 1) * 4;
  const float* qg = H + (size_t)((i0 + row) * 2 + b) * H3 + n * DH;
  const int jr = j0 + row;
  const float* rg = nullptr;
  if (jr < QL)
    rg = RF + (size_t)jr * DM + n * DH;
  else if (jr < JR)
    rg = RB + (size_t)(2046 - jr) * DM + n * DH;
  const float* bias = r_r_bias + n * DH;
  const int tx = tid & 15, ty = tid >> 4;
  float acc[8][8] = {};
  for (int kc = 0; kc < DH; kc += 32) {
#pragma unroll
    for (int kk = 0; kk < 32; kk += 8) {
      int col = kk + c4;
      float4 av = *(const float4*)(qg + kc + col);
      As[col + 0][row] = av.x + bias[kc + col + 0];
      As[col + 1][row] = av.y + bias[kc + col + 1];
      As[col + 2][row] = av.z + bias[kc + col + 2];
      As[col + 3][row] = av.w + bias[kc + col + 3];
      float4 bv = rg ? *(const float4*)(rg + kc + col) : make_float4(0.f, 0.f, 0.f, 0.f);
      Bs[col + 0][row] = bv.x;
      Bs[col + 1][row] = bv.y;
      Bs[col + 2][row] = bv.z;
      Bs[col + 3][row] = bv.w;
    }
    __syncthreads();
#pragma unroll
    for (int k = 0; k < 32; ++k) {
      float a[8], bb[8];
#pragma unroll
      for (int u = 0; u < 8; ++u) a[u] = As[k][ty * 8 + u];
#pragma unroll
      for (int v = 0; v < 8; ++v) bb[v] = Bs[k][tx * 8 + v];
#pragma unroll
      for (int u = 0; u < 8; ++u)
#pragma unroll
        for (int v = 0; v < 8; ++v) acc[u][v] += a[u] * bb[v];
    }
    __syncthreads();
  }
  float* out = BD + (size_t)bn * QL * JR + (size_t)(i0 + ty * 8) * JR + j0 + tx * 8;
#pragma unroll
  for (int u = 0; u < 8; ++u)
#pragma unroll
    for (int v = 0; v < 8; ++v) {
      int j = j0 + tx * 8 + v;
      if (j < JR) out[(size_t)u * JR + v] = acc[u][v];
    }
}

// ========== softmax: P[bn][i][j] = softmax_j((AC + BD_shifted)*SCALE) ======
__global__ void __launch_bounds__(256) softmax_kernel(
    const float* __restrict__ AC, const float* __restrict__ BD,
    const unsigned char* __restrict__ mask, float* __restrict__ P) {
  const int i = blockIdx.x, bn = blockIdx.y, b = bn >> 4;
  const float* ac = AC + ((size_t)bn * QL + i) * QL;
  const float* bd = BD + (size_t)bn * QL * JR + (size_t)i * JR + (QL - 1 - i);
  float* p = P + ((size_t)bn * QL + i) * QL;
  const int tid = threadIdx.x;
  float s[4];
  float mx = -3.4e38f;
#pragma unroll
  for (int t = 0; t < 4; ++t) {
    int j = tid + t * 256;
    float v = (ac[j] + bd[j]) * SCALEF;
    if (mask[j * BATCH + b]) v = -1e30f;
    s[t] = v;
    mx = fmaxf(mx, v);
  }
  __shared__ float red[8];
  __shared__ float red2[8];
#pragma unroll
  for (int o = 16; o; o >>= 1) mx = fmaxf(mx, __shfl_xor_sync(0xffffffffu, mx, o));
  if ((tid & 31) == 0) red[tid >> 5] = mx;
  __syncthreads();
  float bm = red[0];
#pragma unroll
  for (int k = 1; k < 8; ++k) bm = fmaxf(bm, red[k]);
  float sum = 0.f;
#pragma unroll
  for (int t = 0; t < 4; ++t) {
    s[t] = __expf(s[t] - bm);
    sum += s[t];
  }
#pragma unroll
  for (int o = 16; o; o >>= 1) sum += __shfl_xor_sync(0xffffffffu, sum, o);
  if ((tid & 31) == 0) red2[tid >> 5] = sum;
  __syncthreads();
  float tot = 0.f;
#pragma unroll
  for (int k = 0; k < 8; ++k) tot += red2[k];
  float inv = 1.f / tot;
#pragma unroll
  for (int t = 0; t < 4; ++t) p[tid + t * 256] = s[t] * inv;
}

// ========== PV: vec[i,b,n,:] = sum_j P[bn][i][j] * v[j,b,n,:]  =============
__global__ void __launch_bounds__(256) pv_kernel(
    const float* __restrict__ P, const float* __restrict__ H,
    float* __restrict__ V) {
  const int bn = blockIdx.y, b = bn >> 4, n = bn & 15;
  const int i0 = blockIdx.x * 128;
  const int tid = threadIdx.x;
  __shared__ float As[8][128];
  __shared__ float Bs[8][64];
  const int arow = tid >> 1, ac4 = (tid & 1) * 4;
  const int bkk = tid >> 5, bd2 = (tid & 31) * 2;
  const float* Ag = P + ((size_t)bn * QL + i0 + arow) * QL + ac4;
  const int tx = tid & 15, ty = tid >> 4;
  float acc[8][4] = {};
  for (int k0 = 0; k0 < QL; k0 += 8) {
    float4 av = *(const float4*)(Ag + k0);
    As[ac4 + 0][arow] = av.x;
    As[ac4 + 1][arow] = av.y;
    As[ac4 + 2][arow] = av.z;
    As[ac4 + 3][arow] = av.w;
    const float* vg = H + (size_t)((k0 + bkk) * 2 + b) * H3 + 2 * DM + n * DH + bd2;
    float2 bv = *(const float2*)vg;
    Bs[bkk][bd2] = bv.x;
    Bs[bkk][bd2 + 1] = bv.y;
    __syncthreads();
#pragma unroll
    for (int k = 0; k < 8; ++k) {
      float a[8], bb[4];
#pragma unroll
      for (int u = 0; u < 8; ++u) a[u] = As[k][ty * 8 + u];
#pragma unroll
      for (int v = 0; v < 4; ++v) bb[v] = Bs[k][tx * 4 + v];
#pragma unroll
      for (int u = 0; u < 8; ++u)
#pragma unroll
        for (int v = 0; v < 4; ++v) acc[u][v] += a[u] * bb[v];
    }
    __syncthreads();
  }
#pragma unroll
  for (int u = 0; u < 8; ++u) {
    float* out = V + (size_t)((i0 + ty * 8 + u) * 2 + b) * DM + n * DH + tx * 4;
#pragma unroll
    for (int v = 0; v < 4; ++v) out[v] = acc[u][v];
  }
}

// ========== residual + LayerNorm ==========================================
__global__ void __launch_bounds__(256) ln_kernel(
    const float* __restrict__ w, const float* __restrict__ AO,
    const float* __restrict__ gamma, const float* __restrict__ beta,
    float* __restrict__ out) {
  const int row = blockIdx.x;
  const int tid = threadIdx.x;
  const float* x1 = w + (size_t)row * DM;
  const float* x2 = AO + (size_t)row * DM;
  float x[4];
  float s = 0.f, s2 = 0.f;
#pragma unroll
  for (int t = 0; t < 4; ++t) {
    int d = tid + t * 256;
    x[t] = x1[d] + x2[d];
    s += x[t];
    s2 += x[t] * x[t];
  }
  __shared__ float r1[8], r2[8];
#pragma unroll
  for (int o = 16; o; o >>= 1) {
    s += __shfl_xor_sync(0xffffffffu, s, o);
    s2 += __shfl_xor_sync(0xffffffffu, s2, o);
  }
  if ((tid & 31) == 0) { r1[tid >> 5] = s; r2[tid >> 5] = s2; }
  __syncthreads();
  s = 0.f; s2 = 0.f;
#pragma unroll
  for (int k = 0; k < 8; ++k) { s += r1[k]; s2 += r2[k]; }
  const float mu = s * (1.f / DM);
  const float var = s2 * (1.f / DM) - mu * mu;
  const float inv = rsqrtf(var + EPSF);
  float* o = out + (size_t)row * DM;
#pragma unroll
  for (int t = 0; t < 4; ++t) {
    int d = tid + t * 256;
    o[d] = (x[t] - mu) * inv * gamma[d] + beta[d];
  }
}

// ===========================================================================
extern "C" void kernel_launch(void* const* d_in, const int* in_sizes, int n_in,
                              void* d_out, int out_size) {
  const float* w    = (const float*)d_in[0];   // [1024,2,1024]
  const float* r    = (const float*)d_in[1];   // [1024,1024]
  const float* rwb  = (const float*)d_in[2];   // [16,64]
  const float* rrb  = (const float*)d_in[3];   // [16,64]
  const unsigned char* mask = (const unsigned char*)d_in[4];  // [1024,2] bool
  const float* Wqkv = (const float*)d_in[5];   // [1024,3072]
  const float* Wrf  = (const float*)d_in[6];   // [1024,1024]
  const float* Wrb  = (const float*)d_in[7];   // [1024,1024]
  const float* Wo   = (const float*)d_in[8];   // [1024,1024]
  const float* lng  = (const float*)d_in[9];   // [1024]
  const float* lnb  = (const float*)d_in[10];  // [1024]
  float* out = (float*)d_out;                  // [1024,2,1024]

  void* p;
#define SYM(var, sym) cudaGetSymbolAddress(&p, sym); auto* var = (decltype(&sym[0]))p
  SYM(H, g_H); SYM(RF, g_RF); SYM(RB, g_RB); SYM(AC, g_AC); SYM(BD, g_BD);
  SYM(P, g_P); SYM(V, g_V); SYM(AO, g_AO);
  SYM(Awh, g_Awh); SYM(Awl, g_Awl); SYM(rh, g_rh); SYM(rl, g_rl);
  SYM(Vh, g_Vh); SYM(Vl, g_Vl);
  SYM(Wqt_h, g_Wqt_h); SYM(Wqt_l, g_Wqt_l);
  SYM(Wft_h, g_Wft_h); SYM(Wft_l, g_Wft_l);
  SYM(Wbt_h, g_Wbt_h); SYM(Wbt_l, g_Wbt_l);
  SYM(Wot_h, g_Wot_h); SYM(Wot_l, g_Wot_l);
#undef SYM

  // ---- operand prep: split activations, transpose+split weights ----
  split_kernel<<<(QB * DM / 4 + 255) / 256, 256>>>(w, Awh, Awl, QB * DM / 4);
  split_kernel<<<(QL * DM / 4 + 255) / 256, 256>>>(r, rh, rl, QL * DM / 4);
  tsplit_kernel<<<dim3(H3 / 32, DM / 32), dim3(32, 8)>>>(Wqkv, Wqt_h, Wqt_l, DM, H3);
  tsplit_kernel<<<dim3(DM / 32, DM / 32), dim3(32, 8)>>>(Wrf, Wft_h, Wft_l, DM, DM);
  tsplit_kernel<<<dim3(DM / 32, DM / 32), dim3(32, 8)>>>(Wrb, Wbt_h, Wbt_l, DM, DM);
  tsplit_kernel<<<dim3(DM / 32, DM / 32), dim3(32, 8)>>>(Wo, Wot_h, Wot_l, DM, DM);

  // 1) qkv projection: H[2048,3072] = w2d @ W_qkv    (mma.sync bf16 split)
  mma_gemm_nt<<<dim3(H3 / 128, QB / 128), 256>>>(Awh, Awl, Wqt_h, Wqt_l, H, QB, H3, DM);
  // 2) r projections
  mma_gemm_nt<<<dim3(DM / 128, QL / 128), 256>>>(rh, rl, Wft_h, Wft_l, RF, QL, DM, DM);
  mma_gemm_nt<<<dim3(DM / 128, QL / 128), 256>>>(rh, rl, Wbt_h, Wbt_l, RB, QL, DM, DM);
  // 3) AC scores
  ac_kernel<<<dim3(QL / 128, QL / 128, 32), 256>>>(H, rwb, AC);
  // 4) BD raw scores (band-limited)
  bd_kernel<<<dim3((JR + 127) / 128, QL / 128, 32), 256>>>(H, RF, RB, rrb, BD);
  // 5) shift + mask + softmax
  softmax_kernel<<<dim3(QL, 32), 256>>>(AC, BD, mask, P);
  // 6) P @ V
  pv_kernel<<<dim3(QL / 128, 32), 256>>>(P, H, V);
  // 7) output projection
  split_kernel<<<(QB * DM / 4 + 255) / 256, 256>>>(V, Vh, Vl, QB * DM / 4);
  mma_gemm_nt<<<dim3(DM / 128, QB / 128), 256>>>(Vh, Vl, Wot_h, Wot_l, AO, QB, DM, DM);
  // 8) residual + layernorm
  ln_kernel<<<QB, 256>>>(w, AO, lng, lnb, out);
}

// round 10
// speedup vs baseline: 4.0038x; 1.5410x over previous
#include <cuda_runtime.h>
#include <cuda_bf16.h>
#include <cstdint>
#include <cstddef>

#define QL 1024
#define BATCH 2
#define DM 1024
#define NH 16
#define DH 64
#define QB 2048            // Q*B rows
#define H3 3072            // 3*NH*DH
#define JR 2047            // 2*Q-1
#define JRP 2048           // padded
#define SCALEF 0.125f      // 1/sqrt(64)
#define EPSF 1e-5f

// -------- scratch (device globals; no allocations allowed) --------
__device__ float g_H[(size_t)QB * H3];            // qkv heads     25 MB
__device__ float g_RF[(size_t)QL * DM];           // r @ W_r_fw     4 MB
__device__ float g_RB[(size_t)QL * DM];           // r @ W_r_bw     4 MB
__device__ float g_AC[(size_t)32 * QL * QL];      // AC scores    134 MB
__device__ float g_BD[(size_t)32 * QL * JRP];     // BD raw       268 MB
__device__ float g_AO[(size_t)QB * DM];           // attn_out       8 MB

// bf16 hi/lo operands
__device__ __nv_bfloat16 g_Awh[(size_t)QB * DM], g_Awl[(size_t)QB * DM];
__device__ __nv_bfloat16 g_rh[(size_t)QL * DM], g_rl[(size_t)QL * DM];
__device__ __nv_bfloat16 g_Vh[(size_t)QB * DM], g_Vl[(size_t)QB * DM];
__device__ __nv_bfloat16 g_Wqt_h[(size_t)H3 * DM], g_Wqt_l[(size_t)H3 * DM];
__device__ __nv_bfloat16 g_Wft_h[(size_t)DM * DM], g_Wft_l[(size_t)DM * DM];
__device__ __nv_bfloat16 g_Wbt_h[(size_t)DM * DM], g_Wbt_l[(size_t)DM * DM];
__device__ __nv_bfloat16 g_Wot_h[(size_t)DM * DM], g_Wot_l[(size_t)DM * DM];

// attention-core bf16 operands (per-(b,n) K-major layouts)
__device__ __nv_bfloat16 g_Qach[(size_t)32 * QL * DH], g_Qacl[(size_t)32 * QL * DH];
__device__ __nv_bfloat16 g_Qbdh[(size_t)32 * QL * DH], g_Qbdl[(size_t)32 * QL * DH];
__device__ __nv_bfloat16 g_Kh[(size_t)32 * QL * DH],  g_Kl[(size_t)32 * QL * DH];
__device__ __nv_bfloat16 g_VTh[(size_t)32 * DH * QL], g_VTl[(size_t)32 * DH * QL];
__device__ __nv_bfloat16 g_RKh[(size_t)NH * JRP * DH], g_RKl[(size_t)NH * JRP * DH];
__device__ __nv_bfloat16 g_Ph[(size_t)32 * QL * QL], g_Pl[(size_t)32 * QL * QL];

// ======================= small PTX helpers (portable) ======================
__device__ __forceinline__ uint32_t smem_to_u32(const void* p) {
  uint32_t a;
  asm("{ .reg .u64 t; cvta.to.shared.u64 t, %1; cvt.u32.u64 %0, t; }"
      : "=r"(a) : "l"(p));
  return a;
}
__device__ __forceinline__ void ldsm4(uint32_t* r, uint32_t a) {
  asm volatile("ldmatrix.sync.aligned.m8n8.x4.shared.b16 {%0,%1,%2,%3}, [%4];"
               : "=r"(r[0]), "=r"(r[1]), "=r"(r[2]), "=r"(r[3]) : "r"(a));
}
__device__ __forceinline__ void mma_bf16(float* c, const uint32_t* a,
                                         const uint32_t* b) {
  asm volatile(
      "mma.sync.aligned.m16n8k16.row.col.f32.bf16.bf16.f32 "
      "{%0,%1,%2,%3},{%4,%5,%6,%7},{%8,%9},{%0,%1,%2,%3};"
      : "+f"(c[0]), "+f"(c[1]), "+f"(c[2]), "+f"(c[3])
      : "r"(a[0]), "r"(a[1]), "r"(a[2]), "r"(a[3]), "r"(b[0]), "r"(b[1]));
}
__device__ __forceinline__ void split1(float v, __nv_bfloat16& h, __nv_bfloat16& l) {
  h = __float2bfloat16(v);
  l = __float2bfloat16(v - __bfloat162float(h));
}

// ================= elementwise fp32 -> bf16 hi/lo split ====================
__global__ void __launch_bounds__(256) split_kernel(
    const float* __restrict__ X, __nv_bfloat16* __restrict__ Xh,
    __nv_bfloat16* __restrict__ Xl, int n4) {
  int i = blockIdx.x * 256 + threadIdx.x;
  if (i >= n4) return;
  float4 v = ((const float4*)X)[i];
  __nv_bfloat16 h0, h1, h2, h3, l0, l1, l2, l3;
  split1(v.x, h0, l0); split1(v.y, h1, l1);
  split1(v.z, h2, l2); split1(v.w, h3, l3);
  ((__nv_bfloat162*)Xh)[2 * i]     = __halves2bfloat162(h0, h1);
  ((__nv_bfloat162*)Xh)[2 * i + 1] = __halves2bfloat162(h2, h3);
  ((__nv_bfloat162*)Xl)[2 * i]     = __halves2bfloat162(l0, l1);
  ((__nv_bfloat162*)Xl)[2 * i + 1] = __halves2bfloat162(l2, l3);
}

// ============== transpose + split: W[K,N] fp32 -> Wt[N,K] bf16 hi/lo =======
__global__ void __launch_bounds__(256) tsplit_kernel(
    const float* __restrict__ W, __nv_bfloat16* __restrict__ Oht,
    __nv_bfloat16* __restrict__ Olt, int K, int N) {
  __shared__ float t[32][33];
  const int n0 = blockIdx.x * 32, k0 = blockIdx.y * 32;
  const int tx = threadIdx.x, ty = threadIdx.y;
  for (int r = ty; r < 32; r += 8)
    t[r][tx] = W[(size_t)(k0 + r) * N + n0 + tx];
  __syncthreads();
  for (int r = ty; r < 32; r += 8) {
    float v = t[tx][r];  // = W[k0+tx][n0+r]
    __nv_bfloat16 h, l;
    split1(v, h, l);
    size_t o = (size_t)(n0 + r) * K + k0 + tx;
    Oht[o] = h;
    Olt[o] = l;
  }
}

// ============ mma.sync bf16 NT GEMM with hi/lo split (3 terms) =============
// Weight-space GEMM (unchanged, proven): C[M,N] = A[M,K] @ B[N,K]^T
#define STR 40  // smem row stride in bf16 (80B): conflict-free ldmatrix
__global__ void __launch_bounds__(256) mma_gemm_nt(
    const __nv_bfloat16* __restrict__ Ah, const __nv_bfloat16* __restrict__ Al,
    const __nv_bfloat16* __restrict__ Bh, const __nv_bfloat16* __restrict__ Bl,
    float* __restrict__ C, int M, int N, int K) {
  __shared__ __nv_bfloat16 sAh[128 * STR], sAl[128 * STR];
  __shared__ __nv_bfloat16 sBh[128 * STR], sBl[128 * STR];
  const int tid = threadIdx.x, wid = tid >> 5, lane = tid & 31;
  const int m0 = blockIdx.y * 128, n0 = blockIdx.x * 128;
  const int wm = (wid & 3) * 32;
  const int wn = (wid >> 2) * 64;

  const int aRow = wm + (lane & 15);
  const int aCol = (lane >> 4) * 8;
  const int bRow = wn + (lane & 7) + ((lane >> 4) & 1) * 8;
  const int bCol = ((lane >> 3) & 1) * 8;
  const uint32_t aOffH = smem_to_u32(sAh) + (uint32_t)(aRow * STR + aCol) * 2;
  const uint32_t aOffL = smem_to_u32(sAl) + (uint32_t)(aRow * STR + aCol) * 2;
  const uint32_t bOffH = smem_to_u32(sBh) + (uint32_t)(bRow * STR + bCol) * 2;
  const uint32_t bOffL = smem_to_u32(sBl) + (uint32_t)(bRow * STR + bCol) * 2;

  float acc[2][8][4] = {};

  const int row2 = tid >> 2, q2 = (tid & 3) * 8;
  for (int c = 0; c < K; c += 32) {
    __syncthreads();
#pragma unroll
    for (int t = 0; t < 2; ++t) {
      int row = row2 + t * 64;
      size_t ga = (size_t)(m0 + row) * K + c + q2;
      size_t gb = (size_t)(n0 + row) * K + c + q2;
      *(uint4*)&sAh[row * STR + q2] = *(const uint4*)(Ah + ga);
      *(uint4*)&sAl[row * STR + q2] = *(const uint4*)(Al + ga);
      *(uint4*)&sBh[row * STR + q2] = *(const uint4*)(Bh + gb);
      *(uint4*)&sBl[row * STR + q2] = *(const uint4*)(Bl + gb);
    }
    __syncthreads();
#pragma unroll
    for (int ks = 0; ks < 2; ++ks) {
      const uint32_t kso = (uint32_t)(ks * 16) * 2;
      uint32_t ah[2][4], al[2][4], bh[8][2], bl[8][2];
#pragma unroll
      for (int mt = 0; mt < 2; ++mt) {
        const uint32_t mo = (uint32_t)(mt * 16 * STR) * 2;
        ldsm4(ah[mt], aOffH + mo + kso);
        ldsm4(al[mt], aOffL + mo + kso);
      }
#pragma unroll
      for (int np = 0; np < 4; ++np) {
        const uint32_t no = (uint32_t)(np * 16 * STR) * 2;
        uint32_t r[4];
        ldsm4(r, bOffH + no + kso);
        bh[2 * np][0] = r[0]; bh[2 * np][1] = r[1];
        bh[2 * np + 1][0] = r[2]; bh[2 * np + 1][1] = r[3];
        ldsm4(r, bOffL + no + kso);
        bl[2 * np][0] = r[0]; bl[2 * np][1] = r[1];
        bl[2 * np + 1][0] = r[2]; bl[2 * np + 1][1] = r[3];
      }
#pragma unroll
      for (int mt = 0; mt < 2; ++mt)
#pragma unroll
        for (int nt = 0; nt < 8; ++nt) {
          mma_bf16(acc[mt][nt], ah[mt], bh[nt]);
          mma_bf16(acc[mt][nt], ah[mt], bl[nt]);
          mma_bf16(acc[mt][nt], al[mt], bh[nt]);
        }
    }
  }

  const int cr = lane >> 2, cc = (lane & 3) * 2;
#pragma unroll
  for (int mt = 0; mt < 2; ++mt) {
    const int r = m0 + wm + mt * 16 + cr;
#pragma unroll
    for (int nt = 0; nt < 8; ++nt) {
      const int col = n0 + wn + nt * 8 + cc;
      *(float2*)&C[(size_t)r * N + col] = make_float2(acc[mt][nt][0], acc[mt][nt][1]);
      *(float2*)&C[(size_t)(r + 8) * N + col] = make_float2(acc[mt][nt][2], acc[mt][nt][3]);
    }
  }
}

// ============= batched mma core (shared by AC/BD/PV kernels) ===============
// A [128 rows, K] bf16 hi/lo at lda=K; B [BN rows, K] at ldb=K (both K-major,
// pre-offset to the tile). Accumulates into acc[2*NT][4], NT = BN/16.
template <int BN>
__device__ __forceinline__ void mma_core(
    const __nv_bfloat16* __restrict__ Ah, const __nv_bfloat16* __restrict__ Al,
    const __nv_bfloat16* __restrict__ Bh, const __nv_bfloat16* __restrict__ Bl,
    int K, __nv_bfloat16* sAh, __nv_bfloat16* sAl,
    __nv_bfloat16* sBh, __nv_bfloat16* sBl, float (*acc)[4]) {
  constexpr int NT = BN / 16;
  const int tid = threadIdx.x, wid = tid >> 5, lane = tid & 31;
  const int wm = (wid & 3) * 32;
  const int wn = (wid >> 2) * (BN / 2);
  const int aRow = wm + (lane & 15), aCol = (lane >> 4) * 8;
  const int bRow = wn + (lane & 7) + ((lane >> 4) & 1) * 8;
  const int bCol = ((lane >> 3) & 1) * 8;
  const uint32_t aOffH = smem_to_u32(sAh) + (uint32_t)(aRow * STR + aCol) * 2;
  const uint32_t aOffL = smem_to_u32(sAl) + (uint32_t)(aRow * STR + aCol) * 2;
  const uint32_t bOffH = smem_to_u32(sBh) + (uint32_t)(bRow * STR + bCol) * 2;
  const uint32_t bOffL = smem_to_u32(sBl) + (uint32_t)(bRow * STR + bCol) * 2;
  const int row2 = tid >> 2, q2 = (tid & 3) * 8;

  for (int c = 0; c < K; c += 32) {
    __syncthreads();
#pragma unroll
    for (int t = 0; t < 2; ++t) {
      int row = row2 + t * 64;
      size_t ga = (size_t)row * K + c + q2;
      *(uint4*)&sAh[row * STR + q2] = *(const uint4*)(Ah + ga);
      *(uint4*)&sAl[row * STR + q2] = *(const uint4*)(Al + ga);
    }
#pragma unroll
    for (int t = 0; t < BN / 64; ++t) {
      int row = row2 + t * 64;
      size_t gb = (size_t)row * K + c + q2;
      *(uint4*)&sBh[row * STR + q2] = *(const uint4*)(Bh + gb);
      *(uint4*)&sBl[row * STR + q2] = *(const uint4*)(Bl + gb);
    }
    __syncthreads();
#pragma unroll
    for (int ks = 0; ks < 2; ++ks) {
      const uint32_t kso = (uint32_t)(ks * 16) * 2;
      uint32_t ah[2][4], al[2][4], bh[NT][2], bl[NT][2];
#pragma unroll
      for (int mt = 0; mt < 2; ++mt) {
        const uint32_t mo = (uint32_t)(mt * 16 * STR) * 2;
        ldsm4(ah[mt], aOffH + mo + kso);
        ldsm4(al[mt], aOffL + mo + kso);
      }
#pragma unroll
      for (int np = 0; np < NT / 2; ++np) {
        const uint32_t no = (uint32_t)(np * 16 * STR) * 2;
        uint32_t r[4];
        ldsm4(r, bOffH + no + kso);
        bh[2 * np][0] = r[0]; bh[2 * np][1] = r[1];
        bh[2 * np + 1][0] = r[2]; bh[2 * np + 1][1] = r[3];
        ldsm4(r, bOffL + no + kso);
        bl[2 * np][0] = r[0]; bl[2 * np][1] = r[1];
        bl[2 * np + 1][0] = r[2]; bl[2 * np + 1][1] = r[3];
      }
#pragma unroll
      for (int mt = 0; mt < 2; ++mt)
#pragma unroll
        for (int nt = 0; nt < NT; ++nt) {
          mma_bf16(acc[mt * NT + nt], ah[mt], bh[nt]);
          mma_bf16(acc[mt * NT + nt], ah[mt], bl[nt]);
          mma_bf16(acc[mt * NT + nt], al[mt], bh[nt]);
        }
    }
  }
}

// ===== prep_heads: H -> Qac/Qbd/K (per-bn K-major) + VT (transposed) =======
__global__ void __launch_bounds__(256) prep_heads(
    const float* __restrict__ H, const float* __restrict__ rwb,
    const float* __restrict__ rrb,
    __nv_bfloat16* __restrict__ Qach, __nv_bfloat16* __restrict__ Qacl,
    __nv_bfloat16* __restrict__ Qbdh, __nv_bfloat16* __restrict__ Qbdl,
    __nv_bfloat16* __restrict__ Kh, __nv_bfloat16* __restrict__ Kl,
    __nv_bfloat16* __restrict__ VTh, __nv_bfloat16* __restrict__ VTl) {
  const int bn = blockIdx.y, b = bn >> 4, n = bn & 15;
  const int i0 = blockIdx.x * 64;
  const int tid = threadIdx.x;
  __shared__ float vs[64][65];
#pragma unroll
  for (int t = 0; t < 16; ++t) {
    int idx = tid + t * 256;
    int ii = idx >> 6, d = idx & 63;
    int i = i0 + ii;
    size_t hb = (size_t)(i * 2 + b) * H3 + n * DH + d;
    float q = H[hb], k = H[hb + DM], v = H[hb + 2 * DM];
    size_t o = ((size_t)bn * QL + i) * DH + d;
    __nv_bfloat16 h, l;
    split1(q + rwb[n * DH + d], h, l); Qach[o] = h; Qacl[o] = l;
    split1(q + rrb[n * DH + d], h, l); Qbdh[o] = h; Qbdl[o] = l;
    split1(k, h, l); Kh[o] = h; Kl[o] = l;
    vs[ii][d] = v;
  }
  __syncthreads();
#pragma unroll
  for (int t = 0; t < 16; ++t) {
    int idx = tid + t * 256;
    int d = idx >> 6, ii = idx & 63;
    __nv_bfloat16 h, l;
    split1(vs[ii][d], h, l);
    size_t o = ((size_t)bn * DH + d) * QL + i0 + ii;
    VTh[o] = h; VTl[o] = l;
  }
}

// ===== prep_rk: RF/RB -> RK[n][2048pad][64] bf16 hi/lo =====================
__global__ void __launch_bounds__(256) prep_rk(
    const float* __restrict__ RF, const float* __restrict__ RB,
    __nv_bfloat16* __restrict__ RKh, __nv_bfloat16* __restrict__ RKl) {
  const int n = blockIdx.y;
  const int j0 = blockIdx.x * 64;
  const int tid = threadIdx.x;
#pragma unroll
  for (int t = 0; t < 16; ++t) {
    int idx = tid + t * 256;
    int jj = idx >> 6, d = idx & 63;
    int jr = j0 + jj;
    float v = 0.f;
    if (jr < QL) v = RF[(size_t)jr * DM + n * DH + d];
    else if (jr < JR) v = RB[(size_t)(2046 - jr) * DM + n * DH + d];
    __nv_bfloat16 h, l;
    split1(v, h, l);
    size_t o = ((size_t)n * JRP + jr) * DH + d;
    RKh[o] = h; RKl[o] = l;
  }
}

// ================= AC via mma: AC[bn][i][j], K=64 ==========================
__global__ void __launch_bounds__(256) ac_mma(
    const __nv_bfloat16* __restrict__ Qh, const __nv_bfloat16* __restrict__ Ql,
    const __nv_bfloat16* __restrict__ Kh, const __nv_bfloat16* __restrict__ Kl,
    float* __restrict__ AC) {
  __shared__ __nv_bfloat16 sAh[128 * STR], sAl[128 * STR];
  __shared__ __nv_bfloat16 sBh[128 * STR], sBl[128 * STR];
  const int bn = blockIdx.z;
  const size_t ab = ((size_t)bn * QL + blockIdx.y * 128) * DH;
  const size_t bb = ((size_t)bn * QL + blockIdx.x * 128) * DH;
  float acc[16][4] = {};
  mma_core<128>(Qh + ab, Ql + ab, Kh + bb, Kl + bb, DH, sAh, sAl, sBh, sBl, acc);
  const int wid = threadIdx.x >> 5, lane = threadIdx.x & 31;
  const int wm = (wid & 3) * 32, wn = (wid >> 2) * 64;
  const int cr = lane >> 2, cc = (lane & 3) * 2;
  float* C = AC + (size_t)bn * QL * QL + (size_t)(blockIdx.y * 128) * QL + blockIdx.x * 128;
#pragma unroll
  for (int mt = 0; mt < 2; ++mt) {
    const int r = wm + mt * 16 + cr;
#pragma unroll
    for (int nt = 0; nt < 8; ++nt) {
      const int col = wn + nt * 8 + cc;
      *(float2*)&C[(size_t)r * QL + col] = make_float2(acc[mt * 8 + nt][0], acc[mt * 8 + nt][1]);
      *(float2*)&C[(size_t)(r + 8) * QL + col] = make_float2(acc[mt * 8 + nt][2], acc[mt * 8 + nt][3]);
    }
  }
}

// ========= BD via mma: BD[bn][i][jr] (band-limited tiles), K=64 ============
__global__ void __launch_bounds__(256) bd_mma(
    const __nv_bfloat16* __restrict__ Qh, const __nv_bfloat16* __restrict__ Ql,
    const __nv_bfloat16* __restrict__ RKh, const __nv_bfloat16* __restrict__ RKl,
    float* __restrict__ BD) {
  const int i0 = blockIdx.y * 128, n0 = blockIdx.x * 128;
  if (i0 + n0 < 769 || i0 + n0 > 2046) return;  // outside rel-shift band
  __shared__ __nv_bfloat16 sAh[128 * STR], sAl[128 * STR];
  __shared__ __nv_bfloat16 sBh[128 * STR], sBl[128 * STR];
  const int bn = blockIdx.z, n = bn & 15;
  const size_t ab = ((size_t)bn * QL + i0) * DH;
  const size_t bb = ((size_t)n * JRP + n0) * DH;
  float acc[16][4] = {};
  mma_core<128>(Qh + ab, Ql + ab, RKh + bb, RKl + bb, DH, sAh, sAl, sBh, sBl, acc);
  const int wid = threadIdx.x >> 5, lane = threadIdx.x & 31;
  const int wm = (wid & 3) * 32, wn = (wid >> 2) * 64;
  const int cr = lane >> 2, cc = (lane & 3) * 2;
  float* C = BD + (size_t)bn * QL * JRP + (size_t)i0 * JRP + n0;
#pragma unroll
  for (int mt = 0; mt < 2; ++mt) {
    const int r = wm + mt * 16 + cr;
#pragma unroll
    for (int nt = 0; nt < 8; ++nt) {
      const int col = wn + nt * 8 + cc;
      *(float2*)&C[(size_t)r * JRP + col] = make_float2(acc[mt * 8 + nt][0], acc[mt * 8 + nt][1]);
      *(float2*)&C[(size_t)(r + 8) * JRP + col] = make_float2(acc[mt * 8 + nt][2], acc[mt * 8 + nt][3]);
    }
  }
}

// ========== softmax -> bf16 hi/lo P ========================================
__global__ void __launch_bounds__(256) softmax_kernel(
    const float* __restrict__ AC, const float* __restrict__ BD,
    const unsigned char* __restrict__ mask,
    __nv_bfloat16* __restrict__ Ph, __nv_bfloat16* __restrict__ Pl) {
  const int i = blockIdx.x, bn = blockIdx.y, b = bn >> 4;
  const float* ac = AC + ((size_t)bn * QL + i) * QL;
  const float* bd = BD + (size_t)bn * QL * JRP + (size_t)i * JRP + (QL - 1 - i);
  const size_t pb = ((size_t)bn * QL + i) * QL;
  const int tid = threadIdx.x;
  float s[4];
  float mx = -3.4e38f;
#pragma unroll
  for (int t = 0; t < 4; ++t) {
    int j = tid + t * 256;
    float v = (ac[j] + bd[j]) * SCALEF;
    if (mask[j * BATCH + b]) v = -1e30f;
    s[t] = v;
    mx = fmaxf(mx, v);
  }
  __shared__ float red[8];
  __shared__ float red2[8];
#pragma unroll
  for (int o = 16; o; o >>= 1) mx = fmaxf(mx, __shfl_xor_sync(0xffffffffu, mx, o));
  if ((tid & 31) == 0) red[tid >> 5] = mx;
  __syncthreads();
  float bm = red[0];
#pragma unroll
  for (int k = 1; k < 8; ++k) bm = fmaxf(bm, red[k]);
  float sum = 0.f;
#pragma unroll
  for (int t = 0; t < 4; ++t) {
    s[t] = __expf(s[t] - bm);
    sum += s[t];
  }
#pragma unroll
  for (int o = 16; o; o >>= 1) sum += __shfl_xor_sync(0xffffffffu, sum, o);
  if ((tid & 31) == 0) red2[tid >> 5] = sum;
  __syncthreads();
  float tot = 0.f;
#pragma unroll
  for (int k = 0; k < 8; ++k) tot += red2[k];
  float inv = 1.f / tot;
#pragma unroll
  for (int t = 0; t < 4; ++t) {
    float pv_ = s[t] * inv;
    __nv_bfloat16 h, l;
    split1(pv_, h, l);
    Ph[pb + tid + t * 256] = h;
    Pl[pb + tid + t * 256] = l;
  }
}

// ========== PV via mma: V[i,b,n*64+d] = sum_j P[i][j] VT[d][j], K=1024 =====
__global__ void __launch_bounds__(256) pv_mma(
    const __nv_bfloat16* __restrict__ Ph, const __nv_bfloat16* __restrict__ Pl,
    const __nv_bfloat16* __restrict__ VTh, const __nv_bfloat16* __restrict__ VTl,
    __nv_bfloat16* __restrict__ Vh, __nv_bfloat16* __restrict__ Vl) {
  __shared__ __nv_bfloat16 sAh[128 * STR], sAl[128 * STR];
  __shared__ __nv_bfloat16 sBh[64 * STR], sBl[64 * STR];
  const int bn = blockIdx.y, b = bn >> 4, n = bn & 15;
  const size_t ab = ((size_t)bn * QL + blockIdx.x * 128) * QL;
  const size_t bb = (size_t)bn * DH * QL;
  float acc[8][4] = {};
  mma_core<64>(Ph + ab, Pl + ab, VTh + bb, VTl + bb, QL, sAh, sAl, sBh, sBl, acc);
  const int wid = threadIdx.x >> 5, lane = threadIdx.x & 31;
  const int wm = (wid & 3) * 32, wn = (wid >> 2) * 32;
  const int cr = lane >> 2, cc = (lane & 3) * 2;
#pragma unroll
  for (int mt = 0; mt < 2; ++mt) {
    const int i = blockIdx.x * 128 + wm + mt * 16 + cr;
#pragma unroll
    for (int nt = 0; nt < 4; ++nt) {
      const int col = wn + nt * 8 + cc;
#pragma unroll
      for (int hh = 0; hh < 2; ++hh) {
        const int ir = i + hh * 8;
        const size_t o = (size_t)(ir * 2 + b) * DM + n * DH + col;
        float v0 = acc[mt * 4 + nt][hh * 2 + 0];
        float v1 = acc[mt * 4 + nt][hh * 2 + 1];
        __nv_bfloat16 h0, l0, h1, l1;
        split1(v0, h0, l0);
        split1(v1, h1, l1);
        *(__nv_bfloat162*)&Vh[o] = __halves2bfloat162(h0, h1);
        *(__nv_bfloat162*)&Vl[o] = __halves2bfloat162(l0, l1);
      }
    }
  }
}

// ========== residual + LayerNorm ==========================================
__global__ void __launch_bounds__(256) ln_kernel(
    const float* __restrict__ w, const float* __restrict__ AO,
    const float* __restrict__ gamma, const float* __restrict__ beta,
    float* __restrict__ out) {
  const int row = blockIdx.x;
  const int tid = threadIdx.x;
  const float* x1 = w + (size_t)row * DM;
  const float* x2 = AO + (size_t)row * DM;
  float x[4];
  float s = 0.f, s2 = 0.f;
#pragma unroll
  for (int t = 0; t < 4; ++t) {
    int d = tid + t * 256;
    x[t] = x1[d] + x2[d];
    s += x[t];
    s2 += x[t] * x[t];
  }
  __shared__ float r1[8], r2[8];
#pragma unroll
  for (int o = 16; o; o >>= 1) {
    s += __shfl_xor_sync(0xffffffffu, s, o);
    s2 += __shfl_xor_sync(0xffffffffu, s2, o);
  }
  if ((tid & 31) == 0) { r1[tid >> 5] = s; r2[tid >> 5] = s2; }
  __syncthreads();
  s = 0.f; s2 = 0.f;
#pragma unroll
  for (int k = 0; k < 8; ++k) { s += r1[k]; s2 += r2[k]; }
  const float mu = s * (1.f / DM);
  const float var = s2 * (1.f / DM) - mu * mu;
  const float inv = rsqrtf(var + EPSF);
  float* o = out + (size_t)row * DM;
#pragma unroll
  for (int t = 0; t < 4; ++t) {
    int d = tid + t * 256;
    o[d] = (x[t] - mu) * inv * gamma[d] + beta[d];
  }
}

// ===========================================================================
extern "C" void kernel_launch(void* const* d_in, const int* in_sizes, int n_in,
                              void* d_out, int out_size) {
  const float* w    = (const float*)d_in[0];   // [1024,2,1024]
  const float* r    = (const float*)d_in[1];   // [1024,1024]
  const float* rwb  = (const float*)d_in[2];   // [16,64]
  const float* rrb  = (const float*)d_in[3];   // [16,64]
  const unsigned char* mask = (const unsigned char*)d_in[4];  // [1024,2] bool
  const float* Wqkv = (const float*)d_in[5];   // [1024,3072]
  const float* Wrf  = (const float*)d_in[6];   // [1024,1024]
  const float* Wrb  = (const float*)d_in[7];   // [1024,1024]
  const float* Wo   = (const float*)d_in[8];   // [1024,1024]
  const float* lng  = (const float*)d_in[9];   // [1024]
  const float* lnb  = (const float*)d_in[10];  // [1024]
  float* out = (float*)d_out;                  // [1024,2,1024]

  void* p;
#define SYM(var, sym) cudaGetSymbolAddress(&p, sym); auto* var = (decltype(&sym[0]))p
  SYM(H, g_H); SYM(RF, g_RF); SYM(RB, g_RB); SYM(AC, g_AC); SYM(BD, g_BD);
  SYM(AO, g_AO);
  SYM(Awh, g_Awh); SYM(Awl, g_Awl); SYM(rh, g_rh); SYM(rl, g_rl);
  SYM(Vh, g_Vh); SYM(Vl, g_Vl);
  SYM(Wqt_h, g_Wqt_h); SYM(Wqt_l, g_Wqt_l);
  SYM(Wft_h, g_Wft_h); SYM(Wft_l, g_Wft_l);
  SYM(Wbt_h, g_Wbt_h); SYM(Wbt_l, g_Wbt_l);
  SYM(Wot_h, g_Wot_h); SYM(Wot_l, g_Wot_l);
  SYM(Qach, g_Qach); SYM(Qacl, g_Qacl);
  SYM(Qbdh, g_Qbdh); SYM(Qbdl, g_Qbdl);
  SYM(Kh, g_Kh); SYM(Kl, g_Kl);
  SYM(VTh, g_VTh); SYM(VTl, g_VTl);
  SYM(RKh, g_RKh); SYM(RKl, g_RKl);
  SYM(Ph, g_Ph); SYM(Pl, g_Pl);
#undef SYM

  // ---- operand prep: split activations, transpose+split weights ----
  split_kernel<<<(QB * DM / 4 + 255) / 256, 256>>>(w, Awh, Awl, QB * DM / 4);
  split_kernel<<<(QL * DM / 4 + 255) / 256, 256>>>(r, rh, rl, QL * DM / 4);
  tsplit_kernel<<<dim3(H3 / 32, DM / 32), dim3(32, 8)>>>(Wqkv, Wqt_h, Wqt_l, DM, H3);
  tsplit_kernel<<<dim3(DM / 32, DM / 32), dim3(32, 8)>>>(Wrf, Wft_h, Wft_l, DM, DM);
  tsplit_kernel<<<dim3(DM / 32, DM / 32), dim3(32, 8)>>>(Wrb, Wbt_h, Wbt_l, DM, DM);
  tsplit_kernel<<<dim3(DM / 32, DM / 32), dim3(32, 8)>>>(Wo, Wot_h, Wot_l, DM, DM);

  // 1) qkv projection: H[2048,3072] = w2d @ W_qkv    (mma.sync bf16 split)
  mma_gemm_nt<<<dim3(H3 / 128, QB / 128), 256>>>(Awh, Awl, Wqt_h, Wqt_l, H, QB, H3, DM);
  // 2) head prep (bf16 hi/lo per-(b,n) layouts + transposed V)
  prep_heads<<<dim3(QL / 64, 32), 256>>>(H, rwb, rrb, Qach, Qacl, Qbdh, Qbdl,
                                         Kh, Kl, VTh, VTl);
  // 3) r projections + rk table
  mma_gemm_nt<<<dim3(DM / 128, QL / 128), 256>>>(rh, rl, Wft_h, Wft_l, RF, QL, DM, DM);
  mma_gemm_nt<<<dim3(DM / 128, QL / 128), 256>>>(rh, rl, Wbt_h, Wbt_l, RB, QL, DM, DM);
  prep_rk<<<dim3(JRP / 64, NH), 256>>>(RF, RB, RKh, RKl);
  // 4) AC scores (tensor core)
  ac_mma<<<dim3(QL / 128, QL / 128, 32), 256>>>(Qach, Qacl, Kh, Kl, AC);
  // 5) BD raw scores (tensor core, band-limited)
  bd_mma<<<dim3(JRP / 128, QL / 128, 32), 256>>>(Qbdh, Qbdl, RKh, RKl, BD);
  // 6) shift + mask + softmax -> bf16 hi/lo P
  softmax_kernel<<<dim3(QL, 32), 256>>>(AC, BD, mask, Ph, Pl);
  // 7) P @ V (tensor core) -> bf16 hi/lo V directly
  pv_mma<<<dim3(QL / 128, 32), 256>>>(Ph, Pl, VTh, VTl, Vh, Vl);
  // 8) output projection
  mma_gemm_nt<<<dim3(DM / 128, QB / 128), 256>>>(Vh, Vl, Wot_h, Wot_l, AO, QB, DM, DM);
  // 9) residual + layernorm
  ln_kernel<<<QB, 256>>>(w, AO, lng, lnb, out);
}